// round 1
// baseline (speedup 1.0000x reference)
#include <cuda_runtime.h>
#include <math.h>

// Problem constants (Llama-3-8B-like prefill)
#define T_TOK 4096
#define D_MODEL 4096
#define N_Q 32
#define N_KV 8
#define HD 128
#define SEQ 1024
#define BATCH 4
#define GQA 4   // N_Q / N_KV

// Scratch (allocation-free rule: __device__ globals)
__device__ float g_q[T_TOK * N_Q * HD];    // 64 MB
__device__ float g_k[T_TOK * N_KV * HD];   // 16 MB
__device__ float g_v[T_TOK * N_KV * HD];   // 16 MB
__device__ float g_att[T_TOK * N_Q * HD];  // 64 MB

// ---------------------------------------------------------------------------
// Tiled SGEMM: C[M,N] = A[M,K] @ B[K,N], all row-major, M%128==0, N%128==0, K%8==0
// BM=BN=128, BK=8, 256 threads, 8x8 register microtile per thread.
// ---------------------------------------------------------------------------
__global__ __launch_bounds__(256) void sgemm128(const float* __restrict__ A,
                                                const float* __restrict__ B,
                                                float* __restrict__ C,
                                                int M, int N, int K) {
    __shared__ float As[8 * 128];  // transposed: As[k][m]
    __shared__ float Bs[8 * 128];  // Bs[k][n]

    const int tid = threadIdx.x;
    const int tx = tid & 15;   // 0..15  -> 8 cols each
    const int ty = tid >> 4;   // 0..15  -> 8 rows each
    const int row0 = blockIdx.y * 128;
    const int col0 = blockIdx.x * 128;

    // A tile load: 128 rows x 8 cols, one float4 per thread
    const int a_row = tid >> 1;        // 0..127
    const int a_col = (tid & 1) * 4;   // 0 or 4
    // B tile load: 8 rows x 128 cols, one float4 per thread
    const int b_row = tid >> 5;        // 0..7
    const int b_col = (tid & 31) * 4;  // 0..124

    const float* Ag = A + (size_t)(row0 + a_row) * K + a_col;
    const float* Bg = B + (size_t)b_row * N + col0 + b_col;

    float acc[8][8];
#pragma unroll
    for (int i = 0; i < 8; i++)
#pragma unroll
        for (int j = 0; j < 8; j++) acc[i][j] = 0.0f;

    for (int k0 = 0; k0 < K; k0 += 8) {
        float4 av = *(const float4*)(Ag + k0);
        float4 bv = *(const float4*)(Bg + (size_t)k0 * N);

        As[(a_col + 0) * 128 + a_row] = av.x;
        As[(a_col + 1) * 128 + a_row] = av.y;
        As[(a_col + 2) * 128 + a_row] = av.z;
        As[(a_col + 3) * 128 + a_row] = av.w;
        *(float4*)&Bs[b_row * 128 + b_col] = bv;
        __syncthreads();

#pragma unroll
        for (int kk = 0; kk < 8; kk++) {
            float4 a0 = *(float4*)&As[kk * 128 + ty * 8];
            float4 a1 = *(float4*)&As[kk * 128 + ty * 8 + 4];
            float4 b0 = *(float4*)&Bs[kk * 128 + tx * 8];
            float4 b1 = *(float4*)&Bs[kk * 128 + tx * 8 + 4];
            float ar[8] = {a0.x, a0.y, a0.z, a0.w, a1.x, a1.y, a1.z, a1.w};
            float br[8] = {b0.x, b0.y, b0.z, b0.w, b1.x, b1.y, b1.z, b1.w};
#pragma unroll
            for (int i = 0; i < 8; i++)
#pragma unroll
                for (int j = 0; j < 8; j++) acc[i][j] += ar[i] * br[j];
        }
        __syncthreads();
    }

#pragma unroll
    for (int i = 0; i < 8; i++) {
        int crow = row0 + ty * 8 + i;
        float4 c0 = make_float4(acc[i][0], acc[i][1], acc[i][2], acc[i][3]);
        float4 c1 = make_float4(acc[i][4], acc[i][5], acc[i][6], acc[i][7]);
        float* cp = C + (size_t)crow * N + col0 + tx * 8;
        *(float4*)cp = c0;
        *(float4*)(cp + 4) = c1;
    }
}

// ---------------------------------------------------------------------------
// RoPE (NeoX half-split; cos/sin identical for h and h+64 because the
// reference concatenates freqs with itself). head < N_Q -> q, else k.
// ---------------------------------------------------------------------------
__global__ void rope_kernel(const int* __restrict__ pos) {
    int t = blockIdx.x;
    int head = blockIdx.y;             // 0..N_Q+N_KV-1
    int h = threadIdx.x;               // 0..63
    float* buf;
    if (head < N_Q)
        buf = g_q + ((size_t)t * N_Q + head) * HD;
    else
        buf = g_k + ((size_t)t * N_KV + (head - N_Q)) * HD;

    float p = (float)pos[t];
    // inv_freq[h] = 10000^(-(2h)/128) = exp(-(h/64)*ln(10000))
    float f = p * __expf(-((float)h / 64.0f) * 9.210340371976184f);
    float c = cosf(f);
    float s = sinf(f);
    float x1 = buf[h];
    float x2 = buf[h + 64];
    buf[h] = x1 * c - x2 * s;
    buf[h + 64] = x2 * c + x1 * s;
}

// ---------------------------------------------------------------------------
// Causal GQA flash attention, fp32, online softmax.
// Grid: (S/64, N_Q, BATCH). Block: 256 threads.
//   thread: r = tid>>2 (query row in tile), cg = tid&3
//   owns score cols {cg + 4*jj} and output dims {cg + 4*dd} (conflict-free smem)
// ---------------------------------------------------------------------------
#define BM 64
#define BN 64
#define KPAD 132
#define PPAD 68
#define BIG_NEG (-3.0e38f)

__global__ __launch_bounds__(256) void attn_kernel() {
    extern __shared__ float sm[];
    float* Qs = sm;                    // [64][132]
    float* Ks = Qs + BM * KPAD;        // [64][132]
    float* Vs = Ks + BN * KPAD;        // [64][132]
    float* Ps = Vs + BN * KPAD;        // [64][68]

    const int mt = blockIdx.x;         // query tile in sequence
    const int n = blockIdx.y;          // query head
    const int b = blockIdx.z;          // sequence
    const int kvh = n >> 2;            // GQA: KV head
    const int tid = threadIdx.x;
    const int r = tid >> 2;            // 0..63
    const int cg = tid & 3;            // 0..3
    const int m0 = mt * BM;

    // Load Q tile (row stride KPAD=132, 16B aligned so float4 OK)
    for (int i = tid; i < BM * HD / 4; i += 256) {
        int row = i >> 5;
        int c4 = (i & 31) * 4;
        float4 qv = *(const float4*)(g_q +
            (((size_t)(b * SEQ + m0 + row) * N_Q + n) * HD + c4));
        *(float4*)&Qs[row * KPAD + c4] = qv;
    }

    float m_i = BIG_NEG, l_i = 0.0f;
    float acc[32];
#pragma unroll
    for (int d = 0; d < 32; d++) acc[d] = 0.0f;

    const float scale = 0.08838834764831845f;  // 1/sqrt(128)
    const int ntiles = mt + 1;

    for (int jt = 0; jt < ntiles; jt++) {
        __syncthreads();  // protect Ks/Vs reuse (and first-iter Q visibility)
        for (int i = tid; i < BN * HD / 4; i += 256) {
            int row = i >> 5;
            int c4 = (i & 31) * 4;
            size_t gidx = ((size_t)(b * SEQ + jt * BN + row) * N_KV + kvh) * HD + c4;
            *(float4*)&Ks[row * KPAD + c4] = *(const float4*)(g_k + gidx);
            *(float4*)&Vs[row * KPAD + c4] = *(const float4*)(g_v + gidx);
        }
        __syncthreads();

        // Scores: this thread computes cols j = cg + 4*jj, jj = 0..15
        float sc[16];
#pragma unroll
        for (int jj = 0; jj < 16; jj++) sc[jj] = 0.0f;
        for (int h = 0; h < HD; h++) {
            float qv = Qs[r * KPAD + h];
#pragma unroll
            for (int jj = 0; jj < 16; jj++)
                sc[jj] += qv * Ks[(cg + 4 * jj) * KPAD + h];
        }

        // Scale + causal mask + tile row-max
        float tmax = BIG_NEG;
        const bool diag = (jt == mt);
#pragma unroll
        for (int jj = 0; jj < 16; jj++) {
            int j = cg + 4 * jj;
            float s_ = sc[jj] * scale;
            if (diag && j > r) s_ = BIG_NEG;
            sc[jj] = s_;
            tmax = fmaxf(tmax, s_);
        }
        tmax = fmaxf(tmax, __shfl_xor_sync(0xffffffff, tmax, 1));
        tmax = fmaxf(tmax, __shfl_xor_sync(0xffffffff, tmax, 2));

        float m_new = fmaxf(m_i, tmax);
        float corr = __expf(m_i - m_new);
        float lsum = 0.0f;
#pragma unroll
        for (int jj = 0; jj < 16; jj++) {
            float p = __expf(sc[jj] - m_new);
            Ps[r * PPAD + cg + 4 * jj] = p;
            lsum += p;
        }
        lsum += __shfl_xor_sync(0xffffffff, lsum, 1);
        lsum += __shfl_xor_sync(0xffffffff, lsum, 2);
        l_i = l_i * corr + lsum;
        m_i = m_new;
#pragma unroll
        for (int d = 0; d < 32; d++) acc[d] *= corr;

        __syncwarp();  // Ps row r written by 4 lanes of same warp

        // PV: acc[dd] += sum_j P[r][j] * V[j][cg + 4*dd]
        for (int j = 0; j < BN; j++) {
            float p = Ps[r * PPAD + j];
#pragma unroll
            for (int dd = 0; dd < 32; dd++)
                acc[dd] += p * Vs[j * KPAD + cg + 4 * dd];
        }
    }

    float inv_l = 1.0f / l_i;
    float* op = g_att + ((size_t)(b * SEQ + m0 + r) * N_Q + n) * HD;
#pragma unroll
    for (int dd = 0; dd < 32; dd++)
        op[cg + 4 * dd] = acc[dd] * inv_l;
}

// ---------------------------------------------------------------------------
// Launch
// ---------------------------------------------------------------------------
extern "C" void kernel_launch(void* const* d_in, const int* in_sizes, int n_in,
                              void* d_out, int out_size) {
    const float* x  = (const float*)d_in[0];
    const int* pos  = (const int*)d_in[1];
    const float* Wq = (const float*)d_in[2];   // [D, N, H] == [D, N*H] row-major
    const float* Wk = (const float*)d_in[3];   // [D, K*H]
    const float* Wv = (const float*)d_in[4];   // [D, K*H]
    const float* Wo = (const float*)d_in[5];   // [N, H, D] == [N*H, D] row-major
    float* out = (float*)d_out;
    (void)in_sizes; (void)n_in; (void)out_size;

    float *qp, *kp, *vp, *ap;
    cudaGetSymbolAddress((void**)&qp, g_q);
    cudaGetSymbolAddress((void**)&kp, g_k);
    cudaGetSymbolAddress((void**)&vp, g_v);
    cudaGetSymbolAddress((void**)&ap, g_att);

    // QKV projections
    sgemm128<<<dim3(N_Q * HD / 128, T_TOK / 128), 256>>>(x, Wq, qp, T_TOK, N_Q * HD, D_MODEL);
    sgemm128<<<dim3(N_KV * HD / 128, T_TOK / 128), 256>>>(x, Wk, kp, T_TOK, N_KV * HD, D_MODEL);
    sgemm128<<<dim3(N_KV * HD / 128, T_TOK / 128), 256>>>(x, Wv, vp, T_TOK, N_KV * HD, D_MODEL);

    // RoPE on q and k
    rope_kernel<<<dim3(T_TOK, N_Q + N_KV), 64>>>(pos);

    // Attention
    const int smem_bytes = (BM * KPAD + 2 * BN * KPAD + BM * PPAD) * (int)sizeof(float);
    cudaFuncSetAttribute(attn_kernel, cudaFuncAttributeMaxDynamicSharedMemorySize, smem_bytes);
    attn_kernel<<<dim3(SEQ / BM, N_Q, BATCH), 256, smem_bytes>>>();

    // Output projection
    sgemm128<<<dim3(D_MODEL / 128, T_TOK / 128), 256>>>(ap, Wo, out, T_TOK, D_MODEL, D_MODEL);
}

// round 3
// speedup vs baseline: 2.1791x; 2.1791x over previous
#include <cuda_runtime.h>
#include <cstdint>
#include <math.h>

// Problem constants (Llama-3-8B-like prefill)
#define T_TOK 4096
#define D_MODEL 4096
#define N_Q 32
#define N_KV 8
#define HD 128
#define SEQ 1024
#define BATCH 4

// Scratch (allocation-free rule: __device__ globals)
__device__ float g_q[T_TOK * N_Q * HD];    // 64 MB
__device__ float g_k[T_TOK * N_KV * HD];   // 16 MB
__device__ float g_v[T_TOK * N_KV * HD];   // 16 MB
__device__ float g_att[T_TOK * N_Q * HD];  // 64 MB

__device__ __forceinline__ uint32_t f2tf(float f) {
    uint32_t r; asm("cvt.rna.tf32.f32 %0, %1;" : "=r"(r) : "f"(f)); return r;
}

#define MMA_TF32(d, a, b)                                                     \
    asm volatile(                                                             \
        "mma.sync.aligned.m16n8k8.row.col.f32.tf32.tf32.f32 "                 \
        "{%0,%1,%2,%3}, {%4,%5,%6,%7}, {%8,%9}, {%0,%1,%2,%3};"               \
        : "+f"((d)[0]), "+f"((d)[1]), "+f"((d)[2]), "+f"((d)[3])              \
        : "r"((a)[0]), "r"((a)[1]), "r"((a)[2]), "r"((a)[3]),                 \
          "r"((b)[0]), "r"((b)[1]))

// ---------------------------------------------------------------------------
// TF32 mma.sync GEMM: C[M,N] = A[M,K] @ W[K,N], fp32 in/out.
// 128x128 CTA tile, BK=16, 256 threads, 8 warps (2m x 4n), warp tile 64x32.
// SMEM: As[k][m] / Bs[k][n], stride 136 (conflict-free fragment loads).
// Double-buffered with register prefetch.
// ---------------------------------------------------------------------------
#define KSTR 136
__global__ __launch_bounds__(256, 2) void gemm_mma(const float* __restrict__ A,
                                                   const float* __restrict__ W,
                                                   float* __restrict__ C,
                                                   int Kdim, int Ndim) {
    __shared__ uint32_t As[2][16 * KSTR];
    __shared__ uint32_t Bs[2][16 * KSTR];

    const int tid = threadIdx.x;
    const int lane = tid & 31, w = tid >> 5;
    const int g = lane >> 2, tig = lane & 3;
    const int wm = w & 1, wn = w >> 1;       // 2 x 4 warp grid
    const int cm0 = blockIdx.y * 128;
    const int cn0 = blockIdx.x * 128;

    // loader mappings
    const int arow = tid >> 2;       // 0..63 (and +64)
    const int af   = tid & 3;        // float4 index along k (k = 4*af..4*af+3)
    const int brow = tid >> 5;       // k row 0..7 (and +8)
    const int bcol = (tid & 31) * 4; // n offset

    float acc[4][4][4];
#pragma unroll
    for (int i = 0; i < 4; i++)
#pragma unroll
        for (int j = 0; j < 4; j++)
#pragma unroll
            for (int r = 0; r < 4; r++) acc[i][j][r] = 0.0f;

    const float* Ab = A + (size_t)(cm0 + arow) * Kdim + af * 4;
    const float* Wb = W + cn0 + bcol;

    float4 av0, av1, bv0, bv1;
    // load chunk 0
    av0 = *(const float4*)(Ab);
    av1 = *(const float4*)(Ab + (size_t)64 * Kdim);
    bv0 = *(const float4*)(Wb + (size_t)brow * Ndim);
    bv1 = *(const float4*)(Wb + (size_t)(brow + 8) * Ndim);

    const int nchunk = Kdim >> 4;

#define STS_TILES(buf)                                                         \
    do {                                                                       \
        uint32_t* ap = As[buf];                                                \
        ap[(4 * af + 0) * KSTR + arow] = f2tf(av0.x);                          \
        ap[(4 * af + 1) * KSTR + arow] = f2tf(av0.y);                          \
        ap[(4 * af + 2) * KSTR + arow] = f2tf(av0.z);                          \
        ap[(4 * af + 3) * KSTR + arow] = f2tf(av0.w);                          \
        ap[(4 * af + 0) * KSTR + arow + 64] = f2tf(av1.x);                     \
        ap[(4 * af + 1) * KSTR + arow + 64] = f2tf(av1.y);                     \
        ap[(4 * af + 2) * KSTR + arow + 64] = f2tf(av1.z);                     \
        ap[(4 * af + 3) * KSTR + arow + 64] = f2tf(av1.w);                     \
        uint32_t* bp = Bs[buf];                                                \
        *(uint4*)&bp[brow * KSTR + bcol] =                                     \
            make_uint4(f2tf(bv0.x), f2tf(bv0.y), f2tf(bv0.z), f2tf(bv0.w));    \
        *(uint4*)&bp[(brow + 8) * KSTR + bcol] =                               \
            make_uint4(f2tf(bv1.x), f2tf(bv1.y), f2tf(bv1.z), f2tf(bv1.w));    \
    } while (0)

    STS_TILES(0);
    __syncthreads();

    for (int c = 0; c < nchunk; c++) {
        const int buf = c & 1;
        if (c + 1 < nchunk) {
            const float* Ac = Ab + (size_t)(c + 1) * 16;
            av0 = *(const float4*)(Ac);
            av1 = *(const float4*)(Ac + (size_t)64 * Kdim);
            const float* Wc = Wb + (size_t)(c + 1) * 16 * Ndim;
            bv0 = *(const float4*)(Wc + (size_t)brow * Ndim);
            bv1 = *(const float4*)(Wc + (size_t)(brow + 8) * Ndim);
        }

        {
            const uint32_t* a = As[buf];
            const uint32_t* b = Bs[buf];
#pragma unroll
            for (int h = 0; h < 2; h++) {
                uint32_t afr[4][4], bfr[4][2];
#pragma unroll
                for (int fm = 0; fm < 4; fm++) {
                    const uint32_t* r0 = a + (h * 8 + tig) * KSTR + wm * 64 + fm * 16 + g;
                    const uint32_t* r1 = r0 + 4 * KSTR;
                    afr[fm][0] = r0[0];
                    afr[fm][1] = r0[8];
                    afr[fm][2] = r1[0];
                    afr[fm][3] = r1[8];
                }
#pragma unroll
                for (int fn = 0; fn < 4; fn++) {
                    const uint32_t* c0 = b + (h * 8 + tig) * KSTR + wn * 32 + fn * 8 + g;
                    bfr[fn][0] = c0[0];
                    bfr[fn][1] = c0[4 * KSTR];
                }
#pragma unroll
                for (int fm = 0; fm < 4; fm++)
#pragma unroll
                    for (int fn = 0; fn < 4; fn++)
                        MMA_TF32(acc[fm][fn], afr[fm], bfr[fn]);
            }
        }

        if (c + 1 < nchunk) {
            __syncthreads();
            STS_TILES(buf ^ 1);
            __syncthreads();
        }
    }

    // epilogue
    const int m0 = cm0 + wm * 64;
    const int n0 = cn0 + wn * 32;
#pragma unroll
    for (int fm = 0; fm < 4; fm++) {
        int row = m0 + fm * 16 + g;
#pragma unroll
        for (int fn = 0; fn < 4; fn++) {
            int col = n0 + fn * 8 + tig * 2;
            float* cp = C + (size_t)row * Ndim + col;
            *(float2*)cp = make_float2(acc[fm][fn][0], acc[fm][fn][1]);
            *(float2*)(cp + (size_t)8 * Ndim) = make_float2(acc[fm][fn][2], acc[fm][fn][3]);
        }
    }
}

// ---------------------------------------------------------------------------
// RoPE (NeoX half-split). head < N_Q -> q, else k.
// ---------------------------------------------------------------------------
__global__ void rope_kernel(const int* __restrict__ pos) {
    int t = blockIdx.x;
    int head = blockIdx.y;
    int h = threadIdx.x;  // 0..63
    float* buf;
    if (head < N_Q)
        buf = g_q + ((size_t)t * N_Q + head) * HD;
    else
        buf = g_k + ((size_t)t * N_KV + (head - N_Q)) * HD;

    float p = (float)pos[t];
    float f = p * __expf(-((float)h / 64.0f) * 9.210340371976184f);
    float c = cosf(f);
    float s = sinf(f);
    float x1 = buf[h];
    float x2 = buf[h + 64];
    buf[h] = x1 * c - x2 * s;
    buf[h + 64] = x2 * c + x1 * s;
}

// ---------------------------------------------------------------------------
// Causal GQA flash attention, fp32, online softmax (verified in R1).
// ---------------------------------------------------------------------------
#define BM 64
#define BN 64
#define KPAD 132
#define PPAD 68
#define BIG_NEG (-3.0e38f)

__global__ __launch_bounds__(256) void attn_kernel() {
    extern __shared__ float sm[];
    float* Qs = sm;
    float* Ks = Qs + BM * KPAD;
    float* Vs = Ks + BN * KPAD;
    float* Ps = Vs + BN * KPAD;

    const int mt = blockIdx.x;
    const int n = blockIdx.y;
    const int b = blockIdx.z;
    const int kvh = n >> 2;
    const int tid = threadIdx.x;
    const int r = tid >> 2;
    const int cg = tid & 3;
    const int m0 = mt * BM;

    for (int i = tid; i < BM * HD / 4; i += 256) {
        int row = i >> 5;
        int c4 = (i & 31) * 4;
        float4 qv = *(const float4*)(g_q +
            (((size_t)(b * SEQ + m0 + row) * N_Q + n) * HD + c4));
        *(float4*)&Qs[row * KPAD + c4] = qv;
    }

    float m_i = BIG_NEG, l_i = 0.0f;
    float acc[32];
#pragma unroll
    for (int d = 0; d < 32; d++) acc[d] = 0.0f;

    const float scale = 0.08838834764831845f;
    const int ntiles = mt + 1;

    for (int jt = 0; jt < ntiles; jt++) {
        __syncthreads();
        for (int i = tid; i < BN * HD / 4; i += 256) {
            int row = i >> 5;
            int c4 = (i & 31) * 4;
            size_t gidx = ((size_t)(b * SEQ + jt * BN + row) * N_KV + kvh) * HD + c4;
            *(float4*)&Ks[row * KPAD + c4] = *(const float4*)(g_k + gidx);
            *(float4*)&Vs[row * KPAD + c4] = *(const float4*)(g_v + gidx);
        }
        __syncthreads();

        float sc[16];
#pragma unroll
        for (int jj = 0; jj < 16; jj++) sc[jj] = 0.0f;
        for (int h = 0; h < HD; h++) {
            float qv = Qs[r * KPAD + h];
#pragma unroll
            for (int jj = 0; jj < 16; jj++)
                sc[jj] += qv * Ks[(cg + 4 * jj) * KPAD + h];
        }

        float tmax = BIG_NEG;
        const bool diag = (jt == mt);
#pragma unroll
        for (int jj = 0; jj < 16; jj++) {
            int j = cg + 4 * jj;
            float s_ = sc[jj] * scale;
            if (diag && j > r) s_ = BIG_NEG;
            sc[jj] = s_;
            tmax = fmaxf(tmax, s_);
        }
        tmax = fmaxf(tmax, __shfl_xor_sync(0xffffffff, tmax, 1));
        tmax = fmaxf(tmax, __shfl_xor_sync(0xffffffff, tmax, 2));

        float m_new = fmaxf(m_i, tmax);
        float corr = __expf(m_i - m_new);
        float lsum = 0.0f;
#pragma unroll
        for (int jj = 0; jj < 16; jj++) {
            float p = __expf(sc[jj] - m_new);
            Ps[r * PPAD + cg + 4 * jj] = p;
            lsum += p;
        }
        lsum += __shfl_xor_sync(0xffffffff, lsum, 1);
        lsum += __shfl_xor_sync(0xffffffff, lsum, 2);
        l_i = l_i * corr + lsum;
        m_i = m_new;
#pragma unroll
        for (int d = 0; d < 32; d++) acc[d] *= corr;

        __syncwarp();

        for (int j = 0; j < BN; j++) {
            float p = Ps[r * PPAD + j];
#pragma unroll
            for (int dd = 0; dd < 32; dd++)
                acc[dd] += p * Vs[j * KPAD + cg + 4 * dd];
        }
    }

    float inv_l = 1.0f / l_i;
    float* op = g_att + ((size_t)(b * SEQ + m0 + r) * N_Q + n) * HD;
#pragma unroll
    for (int dd = 0; dd < 32; dd++)
        op[cg + 4 * dd] = acc[dd] * inv_l;
}

// ---------------------------------------------------------------------------
// Launch
// ---------------------------------------------------------------------------
extern "C" void kernel_launch(void* const* d_in, const int* in_sizes, int n_in,
                              void* d_out, int out_size) {
    const float* x  = (const float*)d_in[0];
    const int* pos  = (const int*)d_in[1];
    const float* Wq = (const float*)d_in[2];
    const float* Wk = (const float*)d_in[3];
    const float* Wv = (const float*)d_in[4];
    const float* Wo = (const float*)d_in[5];
    float* out = (float*)d_out;
    (void)in_sizes; (void)n_in; (void)out_size;

    float *qp, *kp, *vp, *ap;
    cudaGetSymbolAddress((void**)&qp, g_q);
    cudaGetSymbolAddress((void**)&kp, g_k);
    cudaGetSymbolAddress((void**)&vp, g_v);
    cudaGetSymbolAddress((void**)&ap, g_att);

    // QKV projections (tf32 mma.sync tensor cores)
    gemm_mma<<<dim3(32, 32), 256>>>(x, Wq, qp, D_MODEL, N_Q * HD);
    gemm_mma<<<dim3(8, 32), 256>>>(x, Wk, kp, D_MODEL, N_KV * HD);
    gemm_mma<<<dim3(8, 32), 256>>>(x, Wv, vp, D_MODEL, N_KV * HD);

    // RoPE
    rope_kernel<<<dim3(T_TOK, N_Q + N_KV), 64>>>(pos);

    // Attention
    const int attn_smem = (BM * KPAD + 2 * BN * KPAD + BM * PPAD) * (int)sizeof(float);
    cudaFuncSetAttribute(attn_kernel, cudaFuncAttributeMaxDynamicSharedMemorySize, attn_smem);
    attn_kernel<<<dim3(SEQ / BM, N_Q, BATCH), 256, attn_smem>>>();

    // Output projection
    gemm_mma<<<dim3(32, 32), 256>>>(ap, Wo, out, D_MODEL, D_MODEL);
}

// round 4
// speedup vs baseline: 2.2055x; 1.0121x over previous
#include <cuda_runtime.h>
#include <cstdint>
#include <math.h>

// Problem constants (Llama-3-8B-like prefill)
#define T_TOK 4096
#define D_MODEL 4096
#define N_Q 32
#define N_KV 8
#define HD 128
#define SEQ 1024
#define BATCH 4

// Scratch (allocation-free rule: __device__ globals)
__device__ float g_q[T_TOK * N_Q * HD];    // 64 MB
__device__ float g_k[T_TOK * N_KV * HD];   // 16 MB
__device__ float g_v[T_TOK * N_KV * HD];   // 16 MB
__device__ float g_att[T_TOK * N_Q * HD];  // 64 MB

__device__ __forceinline__ uint32_t f2tf(float f) {
    uint32_t r; asm("cvt.rna.tf32.f32 %0, %1;" : "=r"(r) : "f"(f)); return r;
}

#define MMA_TF32(d, a, b)                                                     \
    asm volatile(                                                             \
        "mma.sync.aligned.m16n8k8.row.col.f32.tf32.tf32.f32 "                 \
        "{%0,%1,%2,%3}, {%4,%5,%6,%7}, {%8,%9}, {%0,%1,%2,%3};"               \
        : "+f"((d)[0]), "+f"((d)[1]), "+f"((d)[2]), "+f"((d)[3])              \
        : "r"((a)[0]), "r"((a)[1]), "r"((a)[2]), "r"((a)[3]),                 \
          "r"((b)[0]), "r"((b)[1]))

// ---------------------------------------------------------------------------
// TF32 mma.sync GEMM: C[M,N] = A[M,K] @ W[K,N], fp32 in/out. (verified R3)
// ---------------------------------------------------------------------------
#define KSTR 136
__global__ __launch_bounds__(256, 2) void gemm_mma(const float* __restrict__ A,
                                                   const float* __restrict__ W,
                                                   float* __restrict__ C,
                                                   int Kdim, int Ndim) {
    __shared__ uint32_t As[2][16 * KSTR];
    __shared__ uint32_t Bs[2][16 * KSTR];

    const int tid = threadIdx.x;
    const int lane = tid & 31, w = tid >> 5;
    const int g = lane >> 2, tig = lane & 3;
    const int wm = w & 1, wn = w >> 1;
    const int cm0 = blockIdx.y * 128;
    const int cn0 = blockIdx.x * 128;

    const int arow = tid >> 2;
    const int af   = tid & 3;
    const int brow = tid >> 5;
    const int bcol = (tid & 31) * 4;

    float acc[4][4][4];
#pragma unroll
    for (int i = 0; i < 4; i++)
#pragma unroll
        for (int j = 0; j < 4; j++)
#pragma unroll
            for (int r = 0; r < 4; r++) acc[i][j][r] = 0.0f;

    const float* Ab = A + (size_t)(cm0 + arow) * Kdim + af * 4;
    const float* Wb = W + cn0 + bcol;

    float4 av0, av1, bv0, bv1;
    av0 = *(const float4*)(Ab);
    av1 = *(const float4*)(Ab + (size_t)64 * Kdim);
    bv0 = *(const float4*)(Wb + (size_t)brow * Ndim);
    bv1 = *(const float4*)(Wb + (size_t)(brow + 8) * Ndim);

    const int nchunk = Kdim >> 4;

#define STS_TILES(buf)                                                         \
    do {                                                                       \
        uint32_t* ap = As[buf];                                                \
        ap[(4 * af + 0) * KSTR + arow] = f2tf(av0.x);                          \
        ap[(4 * af + 1) * KSTR + arow] = f2tf(av0.y);                          \
        ap[(4 * af + 2) * KSTR + arow] = f2tf(av0.z);                          \
        ap[(4 * af + 3) * KSTR + arow] = f2tf(av0.w);                          \
        ap[(4 * af + 0) * KSTR + arow + 64] = f2tf(av1.x);                     \
        ap[(4 * af + 1) * KSTR + arow + 64] = f2tf(av1.y);                     \
        ap[(4 * af + 2) * KSTR + arow + 64] = f2tf(av1.z);                     \
        ap[(4 * af + 3) * KSTR + arow + 64] = f2tf(av1.w);                     \
        uint32_t* bp = Bs[buf];                                                \
        *(uint4*)&bp[brow * KSTR + bcol] =                                     \
            make_uint4(f2tf(bv0.x), f2tf(bv0.y), f2tf(bv0.z), f2tf(bv0.w));    \
        *(uint4*)&bp[(brow + 8) * KSTR + bcol] =                               \
            make_uint4(f2tf(bv1.x), f2tf(bv1.y), f2tf(bv1.z), f2tf(bv1.w));    \
    } while (0)

    STS_TILES(0);
    __syncthreads();

    for (int c = 0; c < nchunk; c++) {
        const int buf = c & 1;
        if (c + 1 < nchunk) {
            const float* Ac = Ab + (size_t)(c + 1) * 16;
            av0 = *(const float4*)(Ac);
            av1 = *(const float4*)(Ac + (size_t)64 * Kdim);
            const float* Wc = Wb + (size_t)(c + 1) * 16 * Ndim;
            bv0 = *(const float4*)(Wc + (size_t)brow * Ndim);
            bv1 = *(const float4*)(Wc + (size_t)(brow + 8) * Ndim);
        }

        {
            const uint32_t* a = As[buf];
            const uint32_t* b = Bs[buf];
#pragma unroll
            for (int h = 0; h < 2; h++) {
                uint32_t afr[4][4], bfr[4][2];
#pragma unroll
                for (int fm = 0; fm < 4; fm++) {
                    const uint32_t* r0 = a + (h * 8 + tig) * KSTR + wm * 64 + fm * 16 + g;
                    const uint32_t* r1 = r0 + 4 * KSTR;
                    afr[fm][0] = r0[0];
                    afr[fm][1] = r0[8];
                    afr[fm][2] = r1[0];
                    afr[fm][3] = r1[8];
                }
#pragma unroll
                for (int fn = 0; fn < 4; fn++) {
                    const uint32_t* c0 = b + (h * 8 + tig) * KSTR + wn * 32 + fn * 8 + g;
                    bfr[fn][0] = c0[0];
                    bfr[fn][1] = c0[4 * KSTR];
                }
#pragma unroll
                for (int fm = 0; fm < 4; fm++)
#pragma unroll
                    for (int fn = 0; fn < 4; fn++)
                        MMA_TF32(acc[fm][fn], afr[fm], bfr[fn]);
            }
        }

        if (c + 1 < nchunk) {
            __syncthreads();
            STS_TILES(buf ^ 1);
            __syncthreads();
        }
    }

    const int m0 = cm0 + wm * 64;
    const int n0 = cn0 + wn * 32;
#pragma unroll
    for (int fm = 0; fm < 4; fm++) {
        int row = m0 + fm * 16 + g;
#pragma unroll
        for (int fn = 0; fn < 4; fn++) {
            int col = n0 + fn * 8 + tig * 2;
            float* cp = C + (size_t)row * Ndim + col;
            *(float2*)cp = make_float2(acc[fm][fn][0], acc[fm][fn][1]);
            *(float2*)(cp + (size_t)8 * Ndim) = make_float2(acc[fm][fn][2], acc[fm][fn][3]);
        }
    }
}

// ---------------------------------------------------------------------------
// RoPE (NeoX half-split). head < N_Q -> q, else k.
// ---------------------------------------------------------------------------
__global__ void rope_kernel(const int* __restrict__ pos) {
    int t = blockIdx.x;
    int head = blockIdx.y;
    int h = threadIdx.x;  // 0..63
    float* buf;
    if (head < N_Q)
        buf = g_q + ((size_t)t * N_Q + head) * HD;
    else
        buf = g_k + ((size_t)t * N_KV + (head - N_Q)) * HD;

    float p = (float)pos[t];
    float f = p * __expf(-((float)h / 64.0f) * 9.210340371976184f);
    float c = cosf(f);
    float s = sinf(f);
    float x1 = buf[h];
    float x2 = buf[h + 64];
    buf[h] = x1 * c - x2 * s;
    buf[h + 64] = x2 * c + x1 * s;
}

// ---------------------------------------------------------------------------
// Flash attention on tensor cores (tf32 mma.sync), causal GQA.
// CTA: 128 q rows x (head, batch). 8 warps, each owns 16 q rows.
// SMEM (uint32 tf32 bits): Qs[128][132], Ks[64][132], Vs[64][136], Ps[128][68]
// All natural layouts; fragments are gathered conflict-free via pads.
// ---------------------------------------------------------------------------
#define QPAD 132
#define KP2 132
#define VPAD 136
#define PP2 68
#define BIG_NEG (-3.0e38f)

__global__ __launch_bounds__(256) void attn_mma() {
    extern __shared__ uint32_t sm4[];
    uint32_t* Qs = sm4;                    // [128][QPAD]
    uint32_t* Ks = Qs + 128 * QPAD;        // [64][KP2]   (kv rows, h cols)
    uint32_t* Vs = Ks + 64 * KP2;          // [64][VPAD]  (kv rows, d cols)
    uint32_t* Ps = Vs + 64 * VPAD;         // [128][PP2]  (q rows, kv cols)

    const int mt = blockIdx.x, n = blockIdx.y, b = blockIdx.z;
    const int kvh = n >> 2;
    const int tid = threadIdx.x, lane = tid & 31, w = tid >> 5;
    const int g = lane >> 2, tig = lane & 3;
    const int m0 = mt * 128;
    const int wrow = w * 16;
    const int wr_min = m0 + wrow;

    // Load Q tile (tf32 convert at store), coalesced
    for (int i = tid; i < 128 * 32; i += 256) {
        int row = i >> 5, c4 = (i & 31) * 4;
        float4 qv = *(const float4*)(g_q +
            ((size_t)(b * SEQ + m0 + row) * N_Q + n) * HD + c4);
        uint32_t* dst = Qs + row * QPAD + c4;
        dst[0] = f2tf(qv.x); dst[1] = f2tf(qv.y);
        dst[2] = f2tf(qv.z); dst[3] = f2tf(qv.w);
    }

    float m_i0 = BIG_NEG, m_i1 = BIG_NEG;
    float l_i0 = 0.0f, l_i1 = 0.0f;
    float o[16][4];
#pragma unroll
    for (int fn = 0; fn < 16; fn++)
#pragma unroll
        for (int r = 0; r < 4; r++) o[fn][r] = 0.0f;

    const float scale = 0.08838834764831845f;  // 1/sqrt(128)
    const int ntiles = 2 * (mt + 1);

    for (int jt = 0; jt < ntiles; jt++) {
        __syncthreads();
        // Load K,V tiles (64 x 128), coalesced, tf32 converted
        for (int i = tid; i < 64 * 32; i += 256) {
            int row = i >> 5, c4 = (i & 31) * 4;
            size_t gidx = ((size_t)(b * SEQ + jt * 64 + row) * N_KV + kvh) * HD + c4;
            float4 kv4 = *(const float4*)(g_k + gidx);
            uint32_t* kd = Ks + row * KP2 + c4;
            kd[0] = f2tf(kv4.x); kd[1] = f2tf(kv4.y);
            kd[2] = f2tf(kv4.z); kd[3] = f2tf(kv4.w);
            float4 vv4 = *(const float4*)(g_v + gidx);
            uint32_t* vd = Vs + row * VPAD + c4;
            vd[0] = f2tf(vv4.x); vd[1] = f2tf(vv4.y);
            vd[2] = f2tf(vv4.z); vd[3] = f2tf(vv4.w);
        }
        __syncthreads();

        if (jt * 64 <= wr_min + 15) {  // warp has at least one unmasked row
            // ---- S = Q K^T (16 x 64) ----
            float s[8][4];
#pragma unroll
            for (int fn = 0; fn < 8; fn++)
#pragma unroll
                for (int r = 0; r < 4; r++) s[fn][r] = 0.0f;

#pragma unroll
            for (int k0 = 0; k0 < 128; k0 += 8) {
                uint32_t a[4];
                const uint32_t* qp = Qs + (wrow + g) * QPAD + k0 + tig;
                a[0] = qp[0]; a[2] = qp[4];
                a[1] = qp[8 * QPAD]; a[3] = qp[8 * QPAD + 4];
#pragma unroll
                for (int fn = 0; fn < 8; fn++) {
                    uint32_t bb[2];
                    const uint32_t* kp = Ks + (fn * 8 + g) * KP2 + k0 + tig;
                    bb[0] = kp[0]; bb[1] = kp[4];
                    MMA_TF32(s[fn], a, bb);
                }
            }

            // ---- softmax on C fragments ----
            const int row0 = wr_min + g, row1 = row0 + 8;
            const bool diag = (jt * 64 + 63 > row0);  // row1 > row0, use row0
            float tm0 = BIG_NEG, tm1 = BIG_NEG;
#pragma unroll
            for (int fn = 0; fn < 8; fn++) {
                int colb = jt * 64 + fn * 8 + 2 * tig;
                float v0 = s[fn][0] * scale;
                float v1 = s[fn][1] * scale;
                float v2 = s[fn][2] * scale;
                float v3 = s[fn][3] * scale;
                if (diag) {
                    if (colb > row0) v0 = BIG_NEG;
                    if (colb + 1 > row0) v1 = BIG_NEG;
                    if (colb > row1) v2 = BIG_NEG;
                    if (colb + 1 > row1) v3 = BIG_NEG;
                }
                s[fn][0] = v0; s[fn][1] = v1; s[fn][2] = v2; s[fn][3] = v3;
                tm0 = fmaxf(tm0, fmaxf(v0, v1));
                tm1 = fmaxf(tm1, fmaxf(v2, v3));
            }
            tm0 = fmaxf(tm0, __shfl_xor_sync(0xffffffff, tm0, 1));
            tm0 = fmaxf(tm0, __shfl_xor_sync(0xffffffff, tm0, 2));
            tm1 = fmaxf(tm1, __shfl_xor_sync(0xffffffff, tm1, 1));
            tm1 = fmaxf(tm1, __shfl_xor_sync(0xffffffff, tm1, 2));

            float mn0 = fmaxf(m_i0, tm0), mn1 = fmaxf(m_i1, tm1);
            float corr0 = __expf(m_i0 - mn0), corr1 = __expf(m_i1 - mn1);
            m_i0 = mn0; m_i1 = mn1;

            float ls0 = 0.0f, ls1 = 0.0f;
            uint32_t* pw = Ps + (wrow + g) * PP2 + 2 * tig;
#pragma unroll
            for (int fn = 0; fn < 8; fn++) {
                float p0 = __expf(s[fn][0] - mn0);
                float p1 = __expf(s[fn][1] - mn0);
                float p2 = __expf(s[fn][2] - mn1);
                float p3 = __expf(s[fn][3] - mn1);
                ls0 += p0 + p1;
                ls1 += p2 + p3;
                pw[fn * 8]     = f2tf(p0);
                pw[fn * 8 + 1] = f2tf(p1);
                pw[8 * PP2 + fn * 8]     = f2tf(p2);
                pw[8 * PP2 + fn * 8 + 1] = f2tf(p3);
            }
            ls0 += __shfl_xor_sync(0xffffffff, ls0, 1);
            ls0 += __shfl_xor_sync(0xffffffff, ls0, 2);
            ls1 += __shfl_xor_sync(0xffffffff, ls1, 1);
            ls1 += __shfl_xor_sync(0xffffffff, ls1, 2);
            l_i0 = l_i0 * corr0 + ls0;
            l_i1 = l_i1 * corr1 + ls1;

#pragma unroll
            for (int fn = 0; fn < 16; fn++) {
                o[fn][0] *= corr0; o[fn][1] *= corr0;
                o[fn][2] *= corr1; o[fn][3] *= corr1;
            }

            __syncwarp();  // P written -> readable cross-lane

            // ---- O += P V (16 x 128) ----
#pragma unroll
            for (int k0 = 0; k0 < 64; k0 += 8) {
                uint32_t a[4];
                const uint32_t* pp = Ps + (wrow + g) * PP2 + k0 + tig;
                a[0] = pp[0]; a[2] = pp[4];
                a[1] = pp[8 * PP2]; a[3] = pp[8 * PP2 + 4];
#pragma unroll
                for (int fn = 0; fn < 16; fn++) {
                    uint32_t bb[2];
                    const uint32_t* vp = Vs + (k0 + tig) * VPAD + fn * 8 + g;
                    bb[0] = vp[0]; bb[1] = vp[4 * VPAD];
                    MMA_TF32(o[fn], a, bb);
                }
            }
            __syncwarp();  // all lanes done reading Ps before next tile rewrite
        }
    }

    // ---- epilogue ----
    float inv0 = 1.0f / l_i0, inv1 = 1.0f / l_i1;
    float* op0 = g_att + ((size_t)(b * SEQ + wr_min + g) * N_Q + n) * HD;
    float* op1 = op0 + (size_t)8 * N_Q * HD;
#pragma unroll
    for (int fn = 0; fn < 16; fn++) {
        int col = fn * 8 + 2 * tig;
        *(float2*)(op0 + col) = make_float2(o[fn][0] * inv0, o[fn][1] * inv0);
        *(float2*)(op1 + col) = make_float2(o[fn][2] * inv1, o[fn][3] * inv1);
    }
}

// ---------------------------------------------------------------------------
// Launch
// ---------------------------------------------------------------------------
extern "C" void kernel_launch(void* const* d_in, const int* in_sizes, int n_in,
                              void* d_out, int out_size) {
    const float* x  = (const float*)d_in[0];
    const int* pos  = (const int*)d_in[1];
    const float* Wq = (const float*)d_in[2];
    const float* Wk = (const float*)d_in[3];
    const float* Wv = (const float*)d_in[4];
    const float* Wo = (const float*)d_in[5];
    float* out = (float*)d_out;
    (void)in_sizes; (void)n_in; (void)out_size;

    float *qp, *kp, *vp, *ap;
    cudaGetSymbolAddress((void**)&qp, g_q);
    cudaGetSymbolAddress((void**)&kp, g_k);
    cudaGetSymbolAddress((void**)&vp, g_v);
    cudaGetSymbolAddress((void**)&ap, g_att);

    // QKV projections (tf32 mma.sync tensor cores)
    gemm_mma<<<dim3(32, 32), 256>>>(x, Wq, qp, D_MODEL, N_Q * HD);
    gemm_mma<<<dim3(8, 32), 256>>>(x, Wk, kp, D_MODEL, N_KV * HD);
    gemm_mma<<<dim3(8, 32), 256>>>(x, Wv, vp, D_MODEL, N_KV * HD);

    // RoPE
    rope_kernel<<<dim3(T_TOK, N_Q + N_KV), 64>>>(pos);

    // Flash attention (tensor cores)
    const int attn_smem = (128 * QPAD + 64 * KP2 + 64 * VPAD + 128 * PP2) * 4;
    cudaFuncSetAttribute(attn_mma, cudaFuncAttributeMaxDynamicSharedMemorySize, attn_smem);
    attn_mma<<<dim3(SEQ / 128, N_Q, BATCH), 256, attn_smem>>>();

    // Output projection
    gemm_mma<<<dim3(32, 32), 256>>>(ap, Wo, out, D_MODEL, D_MODEL);
}

// round 6
// speedup vs baseline: 3.5414x; 1.6057x over previous
#include <cuda_runtime.h>
#include <cstdint>
#include <math.h>

// Problem constants (Llama-3-8B-like prefill)
#define T_TOK 4096
#define D_MODEL 4096
#define N_Q 32
#define N_KV 8
#define HD 128
#define SEQ 1024
#define BATCH 4

// Scratch (allocation-free rule: __device__ globals)
__device__ float g_q[T_TOK * N_Q * HD];    // 64 MB
__device__ float g_k[T_TOK * N_KV * HD];   // 16 MB
__device__ float g_v[T_TOK * N_KV * HD];   // 16 MB
__device__ float g_att[T_TOK * N_Q * HD];  // 64 MB

__device__ __forceinline__ uint32_t f2tf(float f) {
    uint32_t r; asm("cvt.rna.tf32.f32 %0, %1;" : "=r"(r) : "f"(f)); return r;
}

#define MMA_TF32(d, a, b)                                                     \
    asm volatile(                                                             \
        "mma.sync.aligned.m16n8k8.row.col.f32.tf32.tf32.f32 "                 \
        "{%0,%1,%2,%3}, {%4,%5,%6,%7}, {%8,%9}, {%0,%1,%2,%3};"               \
        : "+f"((d)[0]), "+f"((d)[1]), "+f"((d)[2]), "+f"((d)[3])              \
        : "r"((a)[0]), "r"((a)[1]), "r"((a)[2]), "r"((a)[3]),                 \
          "r"((b)[0]), "r"((b)[1]))

// ---------------------------------------------------------------------------
// TF32 mma.sync GEMM: C[M,N] = A[M,K] @ W[K,N], fp32 in/out.
// 128x128 CTA tile, BK=16, 128 threads, 4 warps (2x2), warp tile 64x64.
// SMEM: As[k][m] / Bs[k][n], stride 136 (conflict-free fragment loads).
// Double-buffered, ONE __syncthreads per chunk (STS to idle buffer).
// ---------------------------------------------------------------------------
#define KSTR 136
__global__ __launch_bounds__(128, 2) void gemm_mma(const float* __restrict__ A,
                                                   const float* __restrict__ W,
                                                   float* __restrict__ C,
                                                   int Kdim, int Ndim) {
    __shared__ uint32_t As[2][16 * KSTR];
    __shared__ uint32_t Bs[2][16 * KSTR];

    const int tid = threadIdx.x;
    const int lane = tid & 31, w = tid >> 5;
    const int g = lane >> 2, tig = lane & 3;
    const int wm = w & 1, wn = w >> 1;       // 2x2 warp grid
    const int cm0 = blockIdx.y * 128;
    const int cn0 = blockIdx.x * 128;

    // loader mappings (128 threads, 4 sub-iterations each)
    const int arow = tid >> 2;       // 0..31 (+32,+64,+96)
    const int af   = tid & 3;        // k quad
    const int brow = tid >> 5;       // 0..3 (+4,+8,+12)
    const int bcol = (tid & 31) * 4;

    float acc[4][8][4];
#pragma unroll
    for (int i = 0; i < 4; i++)
#pragma unroll
        for (int j = 0; j < 8; j++)
#pragma unroll
            for (int r = 0; r < 4; r++) acc[i][j][r] = 0.0f;

    const float* Ab = A + (size_t)(cm0 + arow) * Kdim + af * 4;
    const float* Wb = W + cn0 + bcol;

    float4 av[4], bv[4];
#pragma unroll
    for (int gi = 0; gi < 4; gi++) {
        av[gi] = *(const float4*)(Ab + (size_t)(gi * 32) * Kdim);
        bv[gi] = *(const float4*)(Wb + (size_t)(brow + gi * 4) * Ndim);
    }

    const int nchunk = Kdim >> 4;

#define STS_TILES(buf)                                                         \
    do {                                                                       \
        uint32_t* ap = As[buf];                                                \
        _Pragma("unroll")                                                      \
        for (int gi = 0; gi < 4; gi++) {                                       \
            int m = arow + gi * 32;                                            \
            ap[(4 * af + 0) * KSTR + m] = f2tf(av[gi].x);                      \
            ap[(4 * af + 1) * KSTR + m] = f2tf(av[gi].y);                      \
            ap[(4 * af + 2) * KSTR + m] = f2tf(av[gi].z);                      \
            ap[(4 * af + 3) * KSTR + m] = f2tf(av[gi].w);                      \
        }                                                                      \
        uint32_t* bp = Bs[buf];                                                \
        _Pragma("unroll")                                                      \
        for (int gi = 0; gi < 4; gi++) {                                       \
            *(uint4*)&bp[(brow + gi * 4) * KSTR + bcol] =                      \
                make_uint4(f2tf(bv[gi].x), f2tf(bv[gi].y),                     \
                           f2tf(bv[gi].z), f2tf(bv[gi].w));                    \
        }                                                                      \
    } while (0)

    STS_TILES(0);
    __syncthreads();

    for (int c = 0; c < nchunk; c++) {
        const int buf = c & 1;
        const bool more = (c + 1 < nchunk);
        if (more) {
            const float* Ac = Ab + (size_t)(c + 1) * 16;
            const float* Wc = Wb + (size_t)(c + 1) * 16 * Ndim;
#pragma unroll
            for (int gi = 0; gi < 4; gi++) {
                av[gi] = *(const float4*)(Ac + (size_t)(gi * 32) * Kdim);
                bv[gi] = *(const float4*)(Wc + (size_t)(brow + gi * 4) * Ndim);
            }
        }

        {
            const uint32_t* a = As[buf];
            const uint32_t* b = Bs[buf];
#pragma unroll
            for (int h = 0; h < 2; h++) {
                uint32_t afr[4][4], bfr[8][2];
#pragma unroll
                for (int fm = 0; fm < 4; fm++) {
                    const uint32_t* r0 = a + (h * 8 + tig) * KSTR + wm * 64 + fm * 16 + g;
                    const uint32_t* r1 = r0 + 4 * KSTR;
                    afr[fm][0] = r0[0];
                    afr[fm][1] = r0[8];
                    afr[fm][2] = r1[0];
                    afr[fm][3] = r1[8];
                }
#pragma unroll
                for (int fn = 0; fn < 8; fn++) {
                    const uint32_t* c0 = b + (h * 8 + tig) * KSTR + wn * 64 + fn * 8 + g;
                    bfr[fn][0] = c0[0];
                    bfr[fn][1] = c0[4 * KSTR];
                }
#pragma unroll
                for (int fm = 0; fm < 4; fm++)
#pragma unroll
                    for (int fn = 0; fn < 8; fn++)
                        MMA_TF32(acc[fm][fn], afr[fm], bfr[fn]);
            }
        }

        if (more) {
            STS_TILES(buf ^ 1);   // idle buffer: safe, all warps past prior sync
            __syncthreads();
        }
    }

    // epilogue: warp writes its 64x64 tile
    const int m0 = cm0 + wm * 64;
    const int n0 = cn0 + wn * 64;
#pragma unroll
    for (int fm = 0; fm < 4; fm++) {
        int row = m0 + fm * 16 + g;
#pragma unroll
        for (int fn = 0; fn < 8; fn++) {
            int col = n0 + fn * 8 + tig * 2;
            float* cp = C + (size_t)row * Ndim + col;
            *(float2*)cp = make_float2(acc[fm][fn][0], acc[fm][fn][1]);
            *(float2*)(cp + (size_t)8 * Ndim) = make_float2(acc[fm][fn][2], acc[fm][fn][3]);
        }
    }
}

// ---------------------------------------------------------------------------
// RoPE (NeoX half-split). head < N_Q -> q, else k.
// ---------------------------------------------------------------------------
__global__ void rope_kernel(const int* __restrict__ pos) {
    int t = blockIdx.x;
    int head = blockIdx.y;
    int h = threadIdx.x;  // 0..63
    float* buf;
    if (head < N_Q)
        buf = g_q + ((size_t)t * N_Q + head) * HD;
    else
        buf = g_k + ((size_t)t * N_KV + (head - N_Q)) * HD;

    float p = (float)pos[t];
    float f = p * __expf(-((float)h / 64.0f) * 9.210340371976184f);
    float c = cosf(f);
    float s = sinf(f);
    float x1 = buf[h];
    float x2 = buf[h + 64];
    buf[h] = x1 * c - x2 * s;
    buf[h + 64] = x2 * c + x1 * s;
}

// ---------------------------------------------------------------------------
// Flash attention on tensor cores (tf32 mma.sync), causal GQA. (verified R4)
// ---------------------------------------------------------------------------
#define QPAD 132
#define KP2 132
#define VPAD 136
#define PP2 68
#define BIG_NEG (-3.0e38f)

__global__ __launch_bounds__(256) void attn_mma() {
    extern __shared__ uint32_t sm4[];
    uint32_t* Qs = sm4;                    // [128][QPAD]
    uint32_t* Ks = Qs + 128 * QPAD;        // [64][KP2]
    uint32_t* Vs = Ks + 64 * KP2;          // [64][VPAD]
    uint32_t* Ps = Vs + 64 * VPAD;         // [128][PP2]

    const int mt = blockIdx.x, n = blockIdx.y, b = blockIdx.z;
    const int kvh = n >> 2;
    const int tid = threadIdx.x, lane = tid & 31, w = tid >> 5;
    const int g = lane >> 2, tig = lane & 3;
    const int m0 = mt * 128;
    const int wrow = w * 16;
    const int wr_min = m0 + wrow;

    for (int i = tid; i < 128 * 32; i += 256) {
        int row = i >> 5, c4 = (i & 31) * 4;
        float4 qv = *(const float4*)(g_q +
            ((size_t)(b * SEQ + m0 + row) * N_Q + n) * HD + c4);
        uint32_t* dst = Qs + row * QPAD + c4;
        dst[0] = f2tf(qv.x); dst[1] = f2tf(qv.y);
        dst[2] = f2tf(qv.z); dst[3] = f2tf(qv.w);
    }

    float m_i0 = BIG_NEG, m_i1 = BIG_NEG;
    float l_i0 = 0.0f, l_i1 = 0.0f;
    float o[16][4];
#pragma unroll
    for (int fn = 0; fn < 16; fn++)
#pragma unroll
        for (int r = 0; r < 4; r++) o[fn][r] = 0.0f;

    const float scale = 0.08838834764831845f;
    const int ntiles = 2 * (mt + 1);

    for (int jt = 0; jt < ntiles; jt++) {
        __syncthreads();
        for (int i = tid; i < 64 * 32; i += 256) {
            int row = i >> 5, c4 = (i & 31) * 4;
            size_t gidx = ((size_t)(b * SEQ + jt * 64 + row) * N_KV + kvh) * HD + c4;
            float4 kv4 = *(const float4*)(g_k + gidx);
            uint32_t* kd = Ks + row * KP2 + c4;
            kd[0] = f2tf(kv4.x); kd[1] = f2tf(kv4.y);
            kd[2] = f2tf(kv4.z); kd[3] = f2tf(kv4.w);
            float4 vv4 = *(const float4*)(g_v + gidx);
            uint32_t* vd = Vs + row * VPAD + c4;
            vd[0] = f2tf(vv4.x); vd[1] = f2tf(vv4.y);
            vd[2] = f2tf(vv4.z); vd[3] = f2tf(vv4.w);
        }
        __syncthreads();

        if (jt * 64 <= wr_min + 15) {
            float s[8][4];
#pragma unroll
            for (int fn = 0; fn < 8; fn++)
#pragma unroll
                for (int r = 0; r < 4; r++) s[fn][r] = 0.0f;

#pragma unroll
            for (int k0 = 0; k0 < 128; k0 += 8) {
                uint32_t a[4];
                const uint32_t* qp = Qs + (wrow + g) * QPAD + k0 + tig;
                a[0] = qp[0]; a[2] = qp[4];
                a[1] = qp[8 * QPAD]; a[3] = qp[8 * QPAD + 4];
#pragma unroll
                for (int fn = 0; fn < 8; fn++) {
                    uint32_t bb[2];
                    const uint32_t* kp = Ks + (fn * 8 + g) * KP2 + k0 + tig;
                    bb[0] = kp[0]; bb[1] = kp[4];
                    MMA_TF32(s[fn], a, bb);
                }
            }

            const int row0 = wr_min + g, row1 = row0 + 8;
            const bool diag = (jt * 64 + 63 > row0);
            float tm0 = BIG_NEG, tm1 = BIG_NEG;
#pragma unroll
            for (int fn = 0; fn < 8; fn++) {
                int colb = jt * 64 + fn * 8 + 2 * tig;
                float v0 = s[fn][0] * scale;
                float v1 = s[fn][1] * scale;
                float v2 = s[fn][2] * scale;
                float v3 = s[fn][3] * scale;
                if (diag) {
                    if (colb > row0) v0 = BIG_NEG;
                    if (colb + 1 > row0) v1 = BIG_NEG;
                    if (colb > row1) v2 = BIG_NEG;
                    if (colb + 1 > row1) v3 = BIG_NEG;
                }
                s[fn][0] = v0; s[fn][1] = v1; s[fn][2] = v2; s[fn][3] = v3;
                tm0 = fmaxf(tm0, fmaxf(v0, v1));
                tm1 = fmaxf(tm1, fmaxf(v2, v3));
            }
            tm0 = fmaxf(tm0, __shfl_xor_sync(0xffffffff, tm0, 1));
            tm0 = fmaxf(tm0, __shfl_xor_sync(0xffffffff, tm0, 2));
            tm1 = fmaxf(tm1, __shfl_xor_sync(0xffffffff, tm1, 1));
            tm1 = fmaxf(tm1, __shfl_xor_sync(0xffffffff, tm1, 2));

            float mn0 = fmaxf(m_i0, tm0), mn1 = fmaxf(m_i1, tm1);
            float corr0 = __expf(m_i0 - mn0), corr1 = __expf(m_i1 - mn1);
            m_i0 = mn0; m_i1 = mn1;

            float ls0 = 0.0f, ls1 = 0.0f;
            uint32_t* pw = Ps + (wrow + g) * PP2 + 2 * tig;
#pragma unroll
            for (int fn = 0; fn < 8; fn++) {
                float p0 = __expf(s[fn][0] - mn0);
                float p1 = __expf(s[fn][1] - mn0);
                float p2 = __expf(s[fn][2] - mn1);
                float p3 = __expf(s[fn][3] - mn1);
                ls0 += p0 + p1;
                ls1 += p2 + p3;
                pw[fn * 8]     = f2tf(p0);
                pw[fn * 8 + 1] = f2tf(p1);
                pw[8 * PP2 + fn * 8]     = f2tf(p2);
                pw[8 * PP2 + fn * 8 + 1] = f2tf(p3);
            }
            ls0 += __shfl_xor_sync(0xffffffff, ls0, 1);
            ls0 += __shfl_xor_sync(0xffffffff, ls0, 2);
            ls1 += __shfl_xor_sync(0xffffffff, ls1, 1);
            ls1 += __shfl_xor_sync(0xffffffff, ls1, 2);
            l_i0 = l_i0 * corr0 + ls0;
            l_i1 = l_i1 * corr1 + ls1;

#pragma unroll
            for (int fn = 0; fn < 16; fn++) {
                o[fn][0] *= corr0; o[fn][1] *= corr0;
                o[fn][2] *= corr1; o[fn][3] *= corr1;
            }

            __syncwarp();

#pragma unroll
            for (int k0 = 0; k0 < 64; k0 += 8) {
                uint32_t a[4];
                const uint32_t* pp = Ps + (wrow + g) * PP2 + k0 + tig;
                a[0] = pp[0]; a[2] = pp[4];
                a[1] = pp[8 * PP2]; a[3] = pp[8 * PP2 + 4];
#pragma unroll
                for (int fn = 0; fn < 16; fn++) {
                    uint32_t bb[2];
                    const uint32_t* vp = Vs + (k0 + tig) * VPAD + fn * 8 + g;
                    bb[0] = vp[0]; bb[1] = vp[4 * VPAD];
                    MMA_TF32(o[fn], a, bb);
                }
            }
            __syncwarp();
        }
    }

    float inv0 = 1.0f / l_i0, inv1 = 1.0f / l_i1;
    float* op0 = g_att + ((size_t)(b * SEQ + wr_min + g) * N_Q + n) * HD;
    float* op1 = op0 + (size_t)8 * N_Q * HD;
#pragma unroll
    for (int fn = 0; fn < 16; fn++) {
        int col = fn * 8 + 2 * tig;
        *(float2*)(op0 + col) = make_float2(o[fn][0] * inv0, o[fn][1] * inv0);
        *(float2*)(op1 + col) = make_float2(o[fn][2] * inv1, o[fn][3] * inv1);
    }
}

// ---------------------------------------------------------------------------
// Launch
// ---------------------------------------------------------------------------
extern "C" void kernel_launch(void* const* d_in, const int* in_sizes, int n_in,
                              void* d_out, int out_size) {
    const float* x  = (const float*)d_in[0];
    const int* pos  = (const int*)d_in[1];
    const float* Wq = (const float*)d_in[2];
    const float* Wk = (const float*)d_in[3];
    const float* Wv = (const float*)d_in[4];
    const float* Wo = (const float*)d_in[5];
    float* out = (float*)d_out;
    (void)in_sizes; (void)n_in; (void)out_size;

    float *qp, *kp, *vp, *ap;
    cudaGetSymbolAddress((void**)&qp, g_q);
    cudaGetSymbolAddress((void**)&kp, g_k);
    cudaGetSymbolAddress((void**)&vp, g_v);
    cudaGetSymbolAddress((void**)&ap, g_att);

    // QKV projections (tf32 mma.sync tensor cores)
    gemm_mma<<<dim3(32, 32), 128>>>(x, Wq, qp, D_MODEL, N_Q * HD);
    gemm_mma<<<dim3(8, 32), 128>>>(x, Wk, kp, D_MODEL, N_KV * HD);
    gemm_mma<<<dim3(8, 32), 128>>>(x, Wv, vp, D_MODEL, N_KV * HD);

    // RoPE
    rope_kernel<<<dim3(T_TOK, N_Q + N_KV), 64>>>(pos);

    // Flash attention (tensor cores)
    const int attn_smem = (128 * QPAD + 64 * KP2 + 64 * VPAD + 128 * PP2) * 4;
    cudaFuncSetAttribute(attn_mma, cudaFuncAttributeMaxDynamicSharedMemorySize, attn_smem);
    attn_mma<<<dim3(SEQ / 128, N_Q, BATCH), 256, attn_smem>>>();

    // Output projection
    gemm_mma<<<dim3(32, 32), 128>>>(ap, Wo, out, D_MODEL, D_MODEL);
}

// round 8
// speedup vs baseline: 4.2490x; 1.1998x over previous
#include <cuda_runtime.h>
#include <cstdint>
#include <math.h>

// Problem constants (Llama-3-8B-like prefill)
#define T_TOK 4096
#define D_MODEL 4096
#define N_Q 32
#define N_KV 8
#define HD 128
#define SEQ 1024
#define BATCH 4

// Scratch (allocation-free rule: __device__ globals)
__device__ float    g_q[T_TOK * N_Q * HD];       // fp32 -> tf32 bits after rope
__device__ float    g_k[T_TOK * N_KV * HD];
__device__ float    g_v[T_TOK * N_KV * HD];      // fp32 -> tf32 bits after conv
__device__ uint32_t g_att[T_TOK * N_Q * HD];     // tf32 bits (written by attn)
__device__ uint32_t g_xtf[T_TOK * D_MODEL];
__device__ uint32_t g_wqtf[D_MODEL * N_Q * HD];
__device__ uint32_t g_wktf[D_MODEL * N_KV * HD];
__device__ uint32_t g_wvtf[D_MODEL * N_KV * HD];
__device__ uint32_t g_wotf[N_Q * HD * D_MODEL];

__device__ __forceinline__ uint32_t f2tf(float f) {
    uint32_t r; asm("cvt.rna.tf32.f32 %0, %1;" : "=r"(r) : "f"(f)); return r;
}

#define MMA_TF32(d, a, b)                                                     \
    asm volatile(                                                             \
        "mma.sync.aligned.m16n8k8.row.col.f32.tf32.tf32.f32 "                 \
        "{%0,%1,%2,%3}, {%4,%5,%6,%7}, {%8,%9}, {%0,%1,%2,%3};"               \
        : "+f"((d)[0]), "+f"((d)[1]), "+f"((d)[2]), "+f"((d)[3])              \
        : "r"((a)[0]), "r"((a)[1]), "r"((a)[2]), "r"((a)[3]),                 \
          "r"((b)[0]), "r"((b)[1]))

#define CP16(dst, src) \
    asm volatile("cp.async.cg.shared.global [%0], [%1], 16;" :: "r"(dst), "l"(src))
#define CP_COMMIT() asm volatile("cp.async.commit_group;" ::: "memory")

// ---------------------------------------------------------------------------
// Elementwise fp32 -> tf32-bits conversion (also used in-place for v)
// ---------------------------------------------------------------------------
__global__ void conv_tf(const float* in, uint32_t* out, int n4) {
    int i = blockIdx.x * 256 + threadIdx.x;
    if (i < n4) {
        float4 v = ((const float4*)in)[i];
        uint4 o = make_uint4(f2tf(v.x), f2tf(v.y), f2tf(v.z), f2tf(v.w));
        ((uint4*)out)[i] = o;
    }
}

// ---------------------------------------------------------------------------
// TF32 mma.sync GEMM on pre-converted u32 operands.
// C[M,N] = A[M,K] @ W[K,N]; 128x128 CTA tile, BK=16, 128 thr, 4 warps (2x2),
// warp tile 64x64. cp.async 4-stage pipeline, ONE __syncthreads per chunk.
// SMEM per stage: As[m:128][k:16] stride 20, Bs[k:16][n:128] stride 136.
// ---------------------------------------------------------------------------
#define ASTR 20
#define BSTR 136
#define STG (128 * ASTR + 16 * BSTR)   // words per stage = 4736
__global__ __launch_bounds__(128, 2) void gemm_cp(const uint32_t* __restrict__ A,
                                                  const uint32_t* __restrict__ W,
                                                  float* __restrict__ C,
                                                  int Kdim, int Ndim) {
    extern __shared__ uint32_t sh[];
    const uint32_t shb = (uint32_t)__cvta_generic_to_shared(sh);
    const int tid = threadIdx.x, lane = tid & 31, w = tid >> 5;
    const int g = lane >> 2, tig = lane & 3;
    const int wm = w & 1, wn = w >> 1;
    const int cm0 = blockIdx.y * 128, cn0 = blockIdx.x * 128;
    const int nchunk = Kdim >> 4;

    auto load = [&](int c, int s) {
        const uint32_t sb = shb + s * (STG * 4);
#pragma unroll
        for (int i = 0; i < 4; i++) {
            int seg = i * 128 + tid;
            int row = seg >> 2, ks = seg & 3;
            const uint32_t* src = A + (size_t)(cm0 + row) * Kdim + c * 16 + ks * 4;
            CP16(sb + (row * ASTR + ks * 4) * 4, src);
        }
        const uint32_t bb = sb + 128 * ASTR * 4;
#pragma unroll
        for (int i = 0; i < 4; i++) {
            int seg = i * 128 + tid;
            int row = seg >> 5, ns = seg & 31;
            const uint32_t* src = W + (size_t)(c * 16 + row) * Ndim + cn0 + ns * 4;
            CP16(bb + (row * BSTR + ns * 4) * 4, src);
        }
    };

    float acc[4][8][4];
#pragma unroll
    for (int i = 0; i < 4; i++)
#pragma unroll
        for (int j = 0; j < 8; j++)
#pragma unroll
            for (int r = 0; r < 4; r++) acc[i][j][r] = 0.0f;

    load(0, 0); CP_COMMIT();
    load(1, 1); CP_COMMIT();
    load(2, 2); CP_COMMIT();

    for (int c = 0; c < nchunk; c++) {
        asm volatile("cp.async.wait_group 2;" ::: "memory");
        __syncthreads();                       // all threads' chunk-c data visible;
                                               // all warps done with chunk c-1
        if (c + 3 < nchunk) load(c + 3, (c + 3) & 3);
        CP_COMMIT();                           // empty group at tail keeps count exact

        const uint32_t* a = sh + (c & 3) * STG;
        const uint32_t* b = a + 128 * ASTR;
#pragma unroll
        for (int h = 0; h < 2; h++) {
            uint32_t afr[4][4], bfr[8][2];
#pragma unroll
            for (int fm = 0; fm < 4; fm++) {
                const uint32_t* p = a + (wm * 64 + fm * 16 + g) * ASTR + h * 8 + tig;
                afr[fm][0] = p[0];
                afr[fm][1] = p[8 * ASTR];
                afr[fm][2] = p[4];
                afr[fm][3] = p[8 * ASTR + 4];
            }
#pragma unroll
            for (int fn = 0; fn < 8; fn++) {
                const uint32_t* p = b + (h * 8 + tig) * BSTR + wn * 64 + fn * 8 + g;
                bfr[fn][0] = p[0];
                bfr[fn][1] = p[4 * BSTR];
            }
#pragma unroll
            for (int fm = 0; fm < 4; fm++)
#pragma unroll
                for (int fn = 0; fn < 8; fn++)
                    MMA_TF32(acc[fm][fn], afr[fm], bfr[fn]);
        }
    }

    // epilogue: warp writes its 64x64 tile (fp32)
    const int m0 = cm0 + wm * 64;
    const int n0 = cn0 + wn * 64;
#pragma unroll
    for (int fm = 0; fm < 4; fm++) {
        int row = m0 + fm * 16 + g;
#pragma unroll
        for (int fn = 0; fn < 8; fn++) {
            int col = n0 + fn * 8 + tig * 2;
            float* cp = C + (size_t)row * Ndim + col;
            *(float2*)cp = make_float2(acc[fm][fn][0], acc[fm][fn][1]);
            *(float2*)(cp + (size_t)8 * Ndim) = make_float2(acc[fm][fn][2], acc[fm][fn][3]);
        }
    }
}

// ---------------------------------------------------------------------------
// RoPE (NeoX half-split) + in-place tf32 conversion. head < N_Q -> q, else k.
// ---------------------------------------------------------------------------
__global__ void rope_kernel(const int* __restrict__ pos) {
    int t = blockIdx.x;
    int head = blockIdx.y;
    int h = threadIdx.x;  // 0..63
    float* buf;
    if (head < N_Q)
        buf = g_q + ((size_t)t * N_Q + head) * HD;
    else
        buf = g_k + ((size_t)t * N_KV + (head - N_Q)) * HD;

    float p = (float)pos[t];
    float f = p * __expf(-((float)h / 64.0f) * 9.210340371976184f);
    float c = cosf(f);
    float s = sinf(f);
    float x1 = buf[h];
    float x2 = buf[h + 64];
    uint32_t* ub = (uint32_t*)buf;
    ub[h] = f2tf(x1 * c - x2 * s);
    ub[h + 64] = f2tf(x2 * c + x1 * s);
}

// ---------------------------------------------------------------------------
// Flash attention (tf32 mma.sync), causal GQA. Inputs are tf32 bits (u32).
// cp.async tile loads; output written as tf32 bits to g_att.
// ---------------------------------------------------------------------------
#define QPAD 132
#define KP2 132
#define VPAD 136
#define PP2 68
#define BIG_NEG (-3.0e38f)

__global__ __launch_bounds__(256) void attn_mma() {
    extern __shared__ uint32_t sm4[];
    uint32_t* Qs = sm4;                    // [128][QPAD]
    uint32_t* Ks = Qs + 128 * QPAD;        // [64][KP2]
    uint32_t* Vs = Ks + 64 * KP2;          // [64][VPAD]
    uint32_t* Ps = Vs + 64 * VPAD;         // [128][PP2]
    const uint32_t smb = (uint32_t)__cvta_generic_to_shared(sm4);
    const uint32_t QsB = smb;
    const uint32_t KsB = smb + 128 * QPAD * 4;
    const uint32_t VsB = KsB + 64 * KP2 * 4;

    const uint32_t* qsrc = (const uint32_t*)g_q;
    const uint32_t* ksrc = (const uint32_t*)g_k;
    const uint32_t* vsrc = (const uint32_t*)g_v;

    const int mt = blockIdx.x, n = blockIdx.y, b = blockIdx.z;
    const int kvh = n >> 2;
    const int tid = threadIdx.x, lane = tid & 31, w = tid >> 5;
    const int g = lane >> 2, tig = lane & 3;
    const int m0 = mt * 128;
    const int wrow = w * 16;
    const int wr_min = m0 + wrow;

    // Q tile via cp.async (128 rows x 128 u32 = 4096 16B segs / 256 thr)
#pragma unroll
    for (int i = 0; i < 16; i++) {
        int seg = i * 256 + tid;
        int row = seg >> 5, ks = seg & 31;
        const uint32_t* src = qsrc + ((size_t)(b * SEQ + m0 + row) * N_Q + n) * HD + ks * 4;
        CP16(QsB + (row * QPAD + ks * 4) * 4, src);
    }
    CP_COMMIT();

    float m_i0 = BIG_NEG, m_i1 = BIG_NEG;
    float l_i0 = 0.0f, l_i1 = 0.0f;
    float o[16][4];
#pragma unroll
    for (int fn = 0; fn < 16; fn++)
#pragma unroll
        for (int r = 0; r < 4; r++) o[fn][r] = 0.0f;

    const float scale = 0.08838834764831845f;
    const int ntiles = 2 * (mt + 1);

    for (int jt = 0; jt < ntiles; jt++) {
        __syncthreads();   // guard Ks/Vs reuse
#pragma unroll
        for (int i = 0; i < 8; i++) {
            int seg = i * 256 + tid;
            int row = seg >> 5, ks = seg & 31;
            size_t gof = ((size_t)(b * SEQ + jt * 64 + row) * N_KV + kvh) * HD + ks * 4;
            CP16(KsB + (row * KP2 + ks * 4) * 4, ksrc + gof);
            CP16(VsB + (row * VPAD + ks * 4) * 4, vsrc + gof);
        }
        CP_COMMIT();
        asm volatile("cp.async.wait_group 0;" ::: "memory");
        __syncthreads();

        if (jt * 64 <= wr_min + 15) {
            float s[8][4];
#pragma unroll
            for (int fn = 0; fn < 8; fn++)
#pragma unroll
                for (int r = 0; r < 4; r++) s[fn][r] = 0.0f;

#pragma unroll
            for (int k0 = 0; k0 < 128; k0 += 8) {
                uint32_t a[4];
                const uint32_t* qp = Qs + (wrow + g) * QPAD + k0 + tig;
                a[0] = qp[0]; a[2] = qp[4];
                a[1] = qp[8 * QPAD]; a[3] = qp[8 * QPAD + 4];
#pragma unroll
                for (int fn = 0; fn < 8; fn++) {
                    uint32_t bb[2];
                    const uint32_t* kp = Ks + (fn * 8 + g) * KP2 + k0 + tig;
                    bb[0] = kp[0]; bb[1] = kp[4];
                    MMA_TF32(s[fn], a, bb);
                }
            }

            const int row0 = wr_min + g, row1 = row0 + 8;
            const bool diag = (jt * 64 + 63 > row0);
            float tm0 = BIG_NEG, tm1 = BIG_NEG;
#pragma unroll
            for (int fn = 0; fn < 8; fn++) {
                int colb = jt * 64 + fn * 8 + 2 * tig;
                float v0 = s[fn][0] * scale;
                float v1 = s[fn][1] * scale;
                float v2 = s[fn][2] * scale;
                float v3 = s[fn][3] * scale;
                if (diag) {
                    if (colb > row0) v0 = BIG_NEG;
                    if (colb + 1 > row0) v1 = BIG_NEG;
                    if (colb > row1) v2 = BIG_NEG;
                    if (colb + 1 > row1) v3 = BIG_NEG;
                }
                s[fn][0] = v0; s[fn][1] = v1; s[fn][2] = v2; s[fn][3] = v3;
                tm0 = fmaxf(tm0, fmaxf(v0, v1));
                tm1 = fmaxf(tm1, fmaxf(v2, v3));
            }
            tm0 = fmaxf(tm0, __shfl_xor_sync(0xffffffff, tm0, 1));
            tm0 = fmaxf(tm0, __shfl_xor_sync(0xffffffff, tm0, 2));
            tm1 = fmaxf(tm1, __shfl_xor_sync(0xffffffff, tm1, 1));
            tm1 = fmaxf(tm1, __shfl_xor_sync(0xffffffff, tm1, 2));

            float mn0 = fmaxf(m_i0, tm0), mn1 = fmaxf(m_i1, tm1);
            float corr0 = __expf(m_i0 - mn0), corr1 = __expf(m_i1 - mn1);
            m_i0 = mn0; m_i1 = mn1;

            float ls0 = 0.0f, ls1 = 0.0f;
            uint32_t* pw = Ps + (wrow + g) * PP2 + 2 * tig;
#pragma unroll
            for (int fn = 0; fn < 8; fn++) {
                float p0 = __expf(s[fn][0] - mn0);
                float p1 = __expf(s[fn][1] - mn0);
                float p2 = __expf(s[fn][2] - mn1);
                float p3 = __expf(s[fn][3] - mn1);
                ls0 += p0 + p1;
                ls1 += p2 + p3;
                pw[fn * 8]     = f2tf(p0);
                pw[fn * 8 + 1] = f2tf(p1);
                pw[8 * PP2 + fn * 8]     = f2tf(p2);
                pw[8 * PP2 + fn * 8 + 1] = f2tf(p3);
            }
            ls0 += __shfl_xor_sync(0xffffffff, ls0, 1);
            ls0 += __shfl_xor_sync(0xffffffff, ls0, 2);
            ls1 += __shfl_xor_sync(0xffffffff, ls1, 1);
            ls1 += __shfl_xor_sync(0xffffffff, ls1, 2);
            l_i0 = l_i0 * corr0 + ls0;
            l_i1 = l_i1 * corr1 + ls1;

#pragma unroll
            for (int fn = 0; fn < 16; fn++) {
                o[fn][0] *= corr0; o[fn][1] *= corr0;
                o[fn][2] *= corr1; o[fn][3] *= corr1;
            }

            __syncwarp();

#pragma unroll
            for (int k0 = 0; k0 < 64; k0 += 8) {
                uint32_t a[4];
                const uint32_t* pp = Ps + (wrow + g) * PP2 + k0 + tig;
                a[0] = pp[0]; a[2] = pp[4];
                a[1] = pp[8 * PP2]; a[3] = pp[8 * PP2 + 4];
#pragma unroll
                for (int fn = 0; fn < 16; fn++) {
                    uint32_t bb[2];
                    const uint32_t* vp = Vs + (k0 + tig) * VPAD + fn * 8 + g;
                    bb[0] = vp[0]; bb[1] = vp[4 * VPAD];
                    MMA_TF32(o[fn], a, bb);
                }
            }
            __syncwarp();
        }
    }

    // epilogue: write tf32 bits (O-proj consumes them directly)
    float inv0 = 1.0f / l_i0, inv1 = 1.0f / l_i1;
    uint32_t* op0 = g_att + ((size_t)(b * SEQ + wr_min + g) * N_Q + n) * HD;
    uint32_t* op1 = op0 + (size_t)8 * N_Q * HD;
#pragma unroll
    for (int fn = 0; fn < 16; fn++) {
        int col = fn * 8 + 2 * tig;
        *(uint2*)(op0 + col) = make_uint2(f2tf(o[fn][0] * inv0), f2tf(o[fn][1] * inv0));
        *(uint2*)(op1 + col) = make_uint2(f2tf(o[fn][2] * inv1), f2tf(o[fn][3] * inv1));
    }
}

// ---------------------------------------------------------------------------
// Launch
// ---------------------------------------------------------------------------
extern "C" void kernel_launch(void* const* d_in, const int* in_sizes, int n_in,
                              void* d_out, int out_size) {
    const float* x  = (const float*)d_in[0];
    const int* pos  = (const int*)d_in[1];
    const float* Wq = (const float*)d_in[2];
    const float* Wk = (const float*)d_in[3];
    const float* Wv = (const float*)d_in[4];
    const float* Wo = (const float*)d_in[5];
    float* out = (float*)d_out;
    (void)in_sizes; (void)n_in; (void)out_size;

    float *qp, *kp, *vp;
    uint32_t *ap, *xtf, *wqtf, *wktf, *wvtf, *wotf;
    cudaGetSymbolAddress((void**)&qp, g_q);
    cudaGetSymbolAddress((void**)&kp, g_k);
    cudaGetSymbolAddress((void**)&vp, g_v);
    cudaGetSymbolAddress((void**)&ap, g_att);
    cudaGetSymbolAddress((void**)&xtf, g_xtf);
    cudaGetSymbolAddress((void**)&wqtf, g_wqtf);
    cudaGetSymbolAddress((void**)&wktf, g_wktf);
    cudaGetSymbolAddress((void**)&wvtf, g_wvtf);
    cudaGetSymbolAddress((void**)&wotf, g_wotf);

    // Pre-convert operands to tf32 bits
    conv_tf<<<T_TOK * D_MODEL / 1024, 256>>>(x, xtf, T_TOK * D_MODEL / 4);
    conv_tf<<<D_MODEL * N_Q * HD / 1024, 256>>>(Wq, wqtf, D_MODEL * N_Q * HD / 4);
    conv_tf<<<D_MODEL * N_KV * HD / 1024, 256>>>(Wk, wktf, D_MODEL * N_KV * HD / 4);
    conv_tf<<<D_MODEL * N_KV * HD / 1024, 256>>>(Wv, wvtf, D_MODEL * N_KV * HD / 4);
    conv_tf<<<N_Q * HD * D_MODEL / 1024, 256>>>(Wo, wotf, N_Q * HD * D_MODEL / 4);

    const int gemm_smem = 4 * STG * 4;  // 75776 B
    cudaFuncSetAttribute(gemm_cp, cudaFuncAttributeMaxDynamicSharedMemorySize, gemm_smem);

    // QKV projections
    gemm_cp<<<dim3(32, 32), 128, gemm_smem>>>(xtf, wqtf, qp, D_MODEL, N_Q * HD);
    gemm_cp<<<dim3(8, 32), 128, gemm_smem>>>(xtf, wktf, kp, D_MODEL, N_KV * HD);
    gemm_cp<<<dim3(8, 32), 128, gemm_smem>>>(xtf, wvtf, vp, D_MODEL, N_KV * HD);

    // RoPE (+ in-place tf32 conversion of q,k); v converted in place
    rope_kernel<<<dim3(T_TOK, N_Q + N_KV), 64>>>(pos);
    conv_tf<<<T_TOK * N_KV * HD / 1024, 256>>>(vp, (uint32_t*)vp, T_TOK * N_KV * HD / 4);

    // Flash attention (tensor cores) -> tf32 bits in g_att
    const int attn_smem = (128 * QPAD + 64 * KP2 + 64 * VPAD + 128 * PP2) * 4;
    cudaFuncSetAttribute(attn_mma, cudaFuncAttributeMaxDynamicSharedMemorySize, attn_smem);
    attn_mma<<<dim3(SEQ / 128, N_Q, BATCH), 256, attn_smem>>>();

    // Output projection (fp32 out)
    gemm_cp<<<dim3(32, 32), 128, gemm_smem>>>(ap, wotf, out, D_MODEL, D_MODEL);
}